// round 2
// baseline (speedup 1.0000x reference)
#include <cuda_runtime.h>
#include <cstdint>

// Problem dims (fixed by reference)
#define M_ROWS   8192      // 2*4096 flattened batch rows
#define K_DIM    2048      // ACTIVE (in)
#define N_DIM    2048      // ACTIVE (out)
#define IN_COLS  4096      // ORIG_IN
#define OUT_COLS 4096      // ORIG_OUT
#define RANK     16
#define SCALING  2.0f      // 32/16

// Device-global scratch (no allocation allowed in kernel_launch)
__device__ float g_xsel[(size_t)M_ROWS * K_DIM];   // 64 MiB gathered input
__device__ float g_weff[(size_t)N_DIM * K_DIM];    // 16 MiB effective weight

// ---------------------------------------------------------------------------
// Kernel 1: W_eff = W_base + SCALING * (lora_B @ lora_A)
// one thread per (o, a) element; coalesced over a
// ---------------------------------------------------------------------------
__global__ void build_weff(const float* __restrict__ W,
                           const float* __restrict__ A,   // [RANK, K_DIM]
                           const float* __restrict__ B) { // [N_DIM, RANK]
    int idx = blockIdx.x * blockDim.x + threadIdx.x;
    int o = idx >> 11;        // / 2048
    int a = idx & 2047;
    float acc = W[idx];
#pragma unroll
    for (int r = 0; r < RANK; r++)
        acc += SCALING * __ldg(&B[o * RANK + r]) * __ldg(&A[r * K_DIM + a]);
    g_weff[idx] = acc;
}

// ---------------------------------------------------------------------------
// Kernel 2: gather x_sel[n][a] = x[n][in_indices[a]]
// ---------------------------------------------------------------------------
__global__ void gather_x(const float* __restrict__ x,
                         const int* __restrict__ in_idx) {
    int idx = blockIdx.x * blockDim.x + threadIdx.x;
    int n = idx >> 11;
    int a = idx & 2047;
    g_xsel[idx] = __ldg(&x[(size_t)n * IN_COLS + __ldg(&in_idx[a])]);
}

// ---------------------------------------------------------------------------
// Kernel 3: zero entire output (d_out is poisoned with 0xAA)
// ---------------------------------------------------------------------------
__global__ void zero_out(float4* __restrict__ out) {
    int idx = blockIdx.x * blockDim.x + threadIdx.x;
    out[idx] = make_float4(0.f, 0.f, 0.f, 0.f);
}

// ---------------------------------------------------------------------------
// Kernel 4: SGEMM  out[n][out_idx[o]] = sum_k x_sel[n][k]*W_eff[o][k] + b[o]
// 128x128x8 block tile, 256 threads, 8x8 per-thread micro-tile.
// Both operands are K-major (NT gemm).
// ---------------------------------------------------------------------------
__global__ void __launch_bounds__(256, 2)
gemm_scatter(const float* __restrict__ bias,
             const int*   __restrict__ out_idx,
             float*       __restrict__ out) {
    __shared__ float As[8][128];
    __shared__ float Bs[8][128];

    const int t  = threadIdx.x;
    const int tx = t & 15;       // 0..15 -> N micro-tile
    const int ty = t >> 4;       // 0..15 -> M micro-tile
    const int rowBase = blockIdx.y * 128;
    const int colBase = blockIdx.x * 128;

    // global-load mapping: 2 threads cover one row's 8 k-values (float4 each)
    const int lrow = t >> 1;           // 0..127
    const int lc4  = (t & 1) << 2;     // 0 or 4

    const float* Ap = g_xsel + (size_t)(rowBase + lrow) * K_DIM + lc4;
    const float* Bp = g_weff + (size_t)(colBase + lrow) * K_DIM + lc4;

    float acc[8][8];
#pragma unroll
    for (int i = 0; i < 8; i++)
#pragma unroll
        for (int j = 0; j < 8; j++) acc[i][j] = 0.f;

    for (int k0 = 0; k0 < K_DIM; k0 += 8) {
        float4 av = *(const float4*)(Ap + k0);
        float4 bv = *(const float4*)(Bp + k0);
        __syncthreads();
        As[lc4 + 0][lrow] = av.x; As[lc4 + 1][lrow] = av.y;
        As[lc4 + 2][lrow] = av.z; As[lc4 + 3][lrow] = av.w;
        Bs[lc4 + 0][lrow] = bv.x; Bs[lc4 + 1][lrow] = bv.y;
        Bs[lc4 + 2][lrow] = bv.z; Bs[lc4 + 3][lrow] = bv.w;
        __syncthreads();
#pragma unroll
        for (int kk = 0; kk < 8; kk++) {
            float a[8], b[8];
#pragma unroll
            for (int i = 0; i < 8; i++) a[i] = As[kk][ty * 8 + i];
#pragma unroll
            for (int j = 0; j < 8; j++) b[j] = Bs[kk][tx * 8 + j];
#pragma unroll
            for (int i = 0; i < 8; i++)
#pragma unroll
                for (int j = 0; j < 8; j++)
                    acc[i][j] += a[i] * b[j];
        }
    }

    // epilogue: bias + scatter through out_indices (sorted -> decent locality)
    int   oc[8];
    float bv[8];
#pragma unroll
    for (int j = 0; j < 8; j++) {
        int c = colBase + tx * 8 + j;
        oc[j] = __ldg(&out_idx[c]);
        bv[j] = __ldg(&bias[c]);
    }
#pragma unroll
    for (int i = 0; i < 8; i++) {
        int n = rowBase + ty * 8 + i;
        float* orow = out + (size_t)n * OUT_COLS;
#pragma unroll
        for (int j = 0; j < 8; j++)
            orow[oc[j]] = acc[i][j] + bv[j];
    }
}

// ---------------------------------------------------------------------------
extern "C" void kernel_launch(void* const* d_in, const int* in_sizes, int n_in,
                              void* d_out, int out_size) {
    const float* x      = (const float*)d_in[0];
    const float* W      = (const float*)d_in[1];
    const float* b      = (const float*)d_in[2];
    const float* lA     = (const float*)d_in[3];
    const float* lB     = (const float*)d_in[4];
    const int*   in_idx = (const int*)d_in[5];
    const int*   out_idx= (const int*)d_in[6];
    float*       out    = (float*)d_out;

    build_weff<<<(N_DIM * K_DIM) / 256, 256>>>(W, lA, lB);
    gather_x<<<(M_ROWS * K_DIM) / 256, 256>>>(x, in_idx);
    zero_out<<<(M_ROWS * OUT_COLS / 4) / 256, 256>>>((float4*)out);

    dim3 grid(N_DIM / 128, M_ROWS / 128);   // (16, 64)
    gemm_scatter<<<grid, 256>>>(b, out_idx, out);
}

// round 7
// speedup vs baseline: 1.8049x; 1.8049x over previous
#include <cuda_runtime.h>
#include <cuda_bf16.h>
#include <cstdint>

// ---------------------------------------------------------------------------
// Problem dims
// ---------------------------------------------------------------------------
#define M_ROWS   8192
#define K_DIM    2048
#define N_DIM    2048
#define IN_COLS  4096
#define OUT_COLS 4096
#define RANK     16
#define SCALING  2.0f

// GEMM tiling
#define MT       128
#define NT       256
#define KC       64                    // bf16 per chunk = 128 B per row
#define NCHUNK   (K_DIM / KC)          // 32

// SMEM stage layout (bytes)
#define OFF_AH   0
#define OFF_AL   16384
#define OFF_BH   32768
#define OFF_BL   65536
#define STAGE    98304                 // 96 KiB
#define SMEM_BYTES (2 * STAGE)

// ---------------------------------------------------------------------------
// Split-precision operand scratch
// ---------------------------------------------------------------------------
__device__ __nv_bfloat16 g_xhi[(size_t)M_ROWS * K_DIM];
__device__ __nv_bfloat16 g_xlo[(size_t)M_ROWS * K_DIM];
__device__ __nv_bfloat16 g_whi[(size_t)N_DIM * K_DIM];
__device__ __nv_bfloat16 g_wlo[(size_t)N_DIM * K_DIM];

// ---------------------------------------------------------------------------
// PTX helpers (all plain sm_80-class — no sm_103a-only features)
// ---------------------------------------------------------------------------
__device__ __forceinline__ uint32_t smem_u32_of(const void* p) {
    uint32_t a;
    asm("{ .reg .u64 t; cvta.to.shared.u64 t, %1; cvt.u32.u64 %0, t; }"
        : "=r"(a) : "l"(p));
    return a;
}

#define CP16(dst, src) \
    asm volatile("cp.async.cg.shared.global [%0], [%1], 16;" \
                 :: "r"(dst), "l"(src))
#define CP_COMMIT() asm volatile("cp.async.commit_group;" ::: "memory")
#define CP_WAIT(n)  asm volatile("cp.async.wait_group %0;" :: "n"(n) : "memory")

#define LDSM_X4(r0, r1, r2, r3, addr) \
    asm volatile("ldmatrix.sync.aligned.m8n8.x4.shared.b16 {%0,%1,%2,%3}, [%4];" \
                 : "=r"(r0), "=r"(r1), "=r"(r2), "=r"(r3) : "r"(addr))

#define MMA_BF16(d, a, b0, b1) \
    asm volatile("mma.sync.aligned.m16n8k16.row.col.f32.bf16.bf16.f32 " \
                 "{%0,%1,%2,%3}, {%4,%5,%6,%7}, {%8,%9}, {%0,%1,%2,%3};" \
                 : "+f"((d)[0]), "+f"((d)[1]), "+f"((d)[2]), "+f"((d)[3]) \
                 : "r"((a)[0]), "r"((a)[1]), "r"((a)[2]), "r"((a)[3]), \
                   "r"(b0), "r"(b1))

// swizzled byte offset within a tile region: row has 8 x 16B granules
__device__ __forceinline__ uint32_t swz(uint32_t row, uint32_t g) {
    return row * 128u + ((g ^ (row & 7u)) << 4);
}

// ---------------------------------------------------------------------------
// Pre-kernels
// ---------------------------------------------------------------------------
__global__ void prep_w(const float* __restrict__ W,
                       const float* __restrict__ A,
                       const float* __restrict__ B) {
    int idx = blockIdx.x * blockDim.x + threadIdx.x;
    int o = idx >> 11, a = idx & 2047;
    float acc = W[idx];
#pragma unroll
    for (int r = 0; r < RANK; r++)
        acc += SCALING * __ldg(&B[o * RANK + r]) * __ldg(&A[r * K_DIM + a]);
    __nv_bfloat16 hi = __float2bfloat16(acc);
    g_whi[idx] = hi;
    g_wlo[idx] = __float2bfloat16(acc - __bfloat162float(hi));
}

__global__ void prep_x(const float* __restrict__ x,
                       const int* __restrict__ in_idx) {
    int idx = blockIdx.x * blockDim.x + threadIdx.x;
    int n = idx >> 11, a = idx & 2047;
    float v = __ldg(&x[(size_t)n * IN_COLS + __ldg(&in_idx[a])]);
    __nv_bfloat16 hi = __float2bfloat16(v);
    g_xhi[idx] = hi;
    g_xlo[idx] = __float2bfloat16(v - __bfloat162float(hi));
}

__global__ void zero_out(float4* __restrict__ out) {
    int idx = blockIdx.x * blockDim.x + threadIdx.x;
    out[idx] = make_float4(0.f, 0.f, 0.f, 0.f);
}

// ---------------------------------------------------------------------------
// cp.async chunk loader: gmem K-major -> swizzled smem tiles
// 12 x 16B per thread (A hi/lo: 2+2, B hi/lo: 4+4)
// ---------------------------------------------------------------------------
__device__ __forceinline__ void load_chunk(uint32_t su, int s, int tmBase,
                                           int tnBase, int c, int tid) {
    const uint32_t sb = su + s * STAGE;
    const size_t kOff = (size_t)c * KC;
#pragma unroll
    for (int it = 0; it < 2; it++) {          // A: 128 rows x 8 granules
        int u = tid + it * 512;
        int r = u >> 3, g = u & 7;
        size_t goff = (size_t)(tmBase + r) * K_DIM + kOff + g * 8;
        CP16(sb + OFF_AH + swz(r, g), (const char*)(g_xhi + goff));
        CP16(sb + OFF_AL + swz(r, g), (const char*)(g_xlo + goff));
    }
#pragma unroll
    for (int it = 0; it < 4; it++) {          // B: 256 rows x 8 granules
        int u = tid + it * 512;
        int r = u >> 3, g = u & 7;
        size_t goff = (size_t)(tnBase + r) * K_DIM + kOff + g * 8;
        CP16(sb + OFF_BH + swz(r, g), (const char*)(g_whi + goff));
        CP16(sb + OFF_BL + swz(r, g), (const char*)(g_wlo + goff));
    }
}

// ---------------------------------------------------------------------------
// bf16x3 mma.sync GEMM + fused bias/scatter epilogue
// CTA 128x256, 16 warps (4m x 4n), warp tile 32x64
// ---------------------------------------------------------------------------
__global__ void __launch_bounds__(512, 1)
gemm_mma(const float* __restrict__ bias,
         const int*   __restrict__ oidx,
         float*       __restrict__ out) {
    extern __shared__ __align__(128) char smraw[];
    const uint32_t su = smem_u32_of(smraw);

    const int tid  = threadIdx.x;
    const int lane = tid & 31;
    const int wid  = tid >> 5;
    const int mBase = (wid & 3) * 32;     // warp m offset in CTA tile
    const int nBase = (wid >> 2) * 64;    // warp n offset in CTA tile
    const int tnBase = blockIdx.x * NT;
    const int tmBase = blockIdx.y * MT;

    // ldmatrix per-thread row mapping
    // A mats: matSel bit0 -> +8 rows, bit1 -> k-granule +1
    const int matSel = lane >> 3;
    const int aRow0  = mBase + (lane & 7) + (matSel & 1) * 8;   // + mi*16
    const int aGsel  = (matSel >> 1) & 1;
    // B mats: matSel bit1 -> +8 n-rows, bit0 -> k-granule +1
    const int bRow0  = nBase + (lane & 7) + ((matSel >> 1) & 1) * 8; // + nj*16
    const int bGsel  = matSel & 1;

    float acc[2][8][4];
#pragma unroll
    for (int i = 0; i < 2; i++)
#pragma unroll
        for (int j = 0; j < 8; j++)
#pragma unroll
            for (int q = 0; q < 4; q++) acc[i][j][q] = 0.f;

    load_chunk(su, 0, tmBase, tnBase, 0, tid);
    CP_COMMIT();

    for (int c = 0; c < NCHUNK; c++) {
        const int s = c & 1;
        if (c + 1 < NCHUNK) {
            load_chunk(su, s ^ 1, tmBase, tnBase, c + 1, tid);
            CP_COMMIT();
            CP_WAIT(1);
        } else {
            CP_WAIT(0);
        }
        __syncthreads();

        const uint32_t sb = su + s * STAGE;
#pragma unroll
        for (int ks = 0; ks < 4; ks++) {
            const uint32_t gA = 2 * ks + aGsel;
            const uint32_t gB = 2 * ks + bGsel;
            uint32_t aH[2][4], aL[2][4];
#pragma unroll
            for (int mi = 0; mi < 2; mi++) {
                const uint32_t r = aRow0 + mi * 16;
                const uint32_t off = swz(r, gA);
                LDSM_X4(aH[mi][0], aH[mi][1], aH[mi][2], aH[mi][3],
                        sb + OFF_AH + off);
                LDSM_X4(aL[mi][0], aL[mi][1], aL[mi][2], aL[mi][3],
                        sb + OFF_AL + off);
            }
#pragma unroll
            for (int nj = 0; nj < 4; nj++) {
                const uint32_t r = bRow0 + nj * 16;
                const uint32_t off = swz(r, gB);
                uint32_t bh[4], bl[4];
                LDSM_X4(bh[0], bh[1], bh[2], bh[3], sb + OFF_BH + off);
                LDSM_X4(bl[0], bl[1], bl[2], bl[3], sb + OFF_BL + off);
#pragma unroll
                for (int mi = 0; mi < 2; mi++) {
                    MMA_BF16(acc[mi][nj * 2 + 0], aH[mi], bh[0], bh[1]);
                    MMA_BF16(acc[mi][nj * 2 + 1], aH[mi], bh[2], bh[3]);
                    MMA_BF16(acc[mi][nj * 2 + 0], aH[mi], bl[0], bl[1]);
                    MMA_BF16(acc[mi][nj * 2 + 1], aH[mi], bl[2], bl[3]);
                    MMA_BF16(acc[mi][nj * 2 + 0], aL[mi], bh[0], bh[1]);
                    MMA_BF16(acc[mi][nj * 2 + 1], aL[mi], bh[2], bh[3]);
                }
            }
        }
        __syncthreads();
    }

    // epilogue: bias + scatter straight from registers
#pragma unroll
    for (int mi = 0; mi < 2; mi++) {
        const int mRow = tmBase + mBase + mi * 16 + (lane >> 2);
        float* orow0 = out + (size_t)mRow * OUT_COLS;
        float* orow1 = out + (size_t)(mRow + 8) * OUT_COLS;
#pragma unroll
        for (int nf = 0; nf < 8; nf++) {
            const int nCol = tnBase + nBase + (nf >> 1) * 16 + (nf & 1) * 8
                           + (lane & 3) * 2;
            const int o0 = __ldg(&oidx[nCol]);
            const int o1 = __ldg(&oidx[nCol + 1]);
            const float b0 = __ldg(&bias[nCol]);
            const float b1 = __ldg(&bias[nCol + 1]);
            orow0[o0] = acc[mi][nf][0] + b0;
            orow0[o1] = acc[mi][nf][1] + b1;
            orow1[o0] = acc[mi][nf][2] + b0;
            orow1[o1] = acc[mi][nf][3] + b1;
        }
    }
}

// ---------------------------------------------------------------------------
extern "C" void kernel_launch(void* const* d_in, const int* in_sizes, int n_in,
                              void* d_out, int out_size) {
    const float* x       = (const float*)d_in[0];
    const float* W       = (const float*)d_in[1];
    const float* b       = (const float*)d_in[2];
    const float* lA      = (const float*)d_in[3];
    const float* lB      = (const float*)d_in[4];
    const int*   in_idx  = (const int*)d_in[5];
    const int*   out_idx = (const int*)d_in[6];
    float*       out     = (float*)d_out;

    cudaFuncSetAttribute(gemm_mma, cudaFuncAttributeMaxDynamicSharedMemorySize,
                         SMEM_BYTES);

    prep_w<<<(N_DIM * K_DIM) / 256, 256>>>(W, lA, lB);
    prep_x<<<(M_ROWS * K_DIM) / 256, 256>>>(x, in_idx);
    zero_out<<<(M_ROWS * OUT_COLS / 4) / 256, 256>>>((float4*)out);

    dim3 grid(N_DIM / NT, M_ROWS / MT);   // (8, 64)
    gemm_mma<<<grid, 512, SMEM_BYTES>>>(b, out_idx, out);
}

// round 9
// speedup vs baseline: 3.8132x; 2.1127x over previous
#include <cuda_runtime.h>
#include <cuda_fp16.h>
#include <cstdint>

// ---------------------------------------------------------------------------
// Problem dims
// ---------------------------------------------------------------------------
#define M_ROWS   8192
#define K_DIM    2048
#define N_DIM    2048
#define IN_COLS  4096
#define OUT_COLS 4096
#define RANK     16
#define SCALING  2.0f

// GEMM tiling: CTA 128x128, 8 warps (2m x 4n), warp tile 64x32
#define MT       128
#define NT       128
#define KC       64                    // fp16 per chunk = 128 B per row
#define NCHUNK   (K_DIM / KC)          // 32
#define STAGES   4
#define NTHREADS 256

// SMEM stage layout (bytes): A(X) 16K, B(W hi) 16K, B(W lo) 16K
#define OFF_A    0
#define OFF_BH   16384
#define OFF_BL   32768
#define STAGE    49152
#define SMEM_BYTES (STAGES * STAGE)    // 192 KiB

// ---------------------------------------------------------------------------
// Operand scratch: X single fp16, W split hi/lo fp16
// ---------------------------------------------------------------------------
__device__ __half g_xh[(size_t)M_ROWS * K_DIM];
__device__ __half g_wh[(size_t)N_DIM * K_DIM];
__device__ __half g_wl[(size_t)N_DIM * K_DIM];

// ---------------------------------------------------------------------------
// PTX helpers (plain sm_80-class only)
// ---------------------------------------------------------------------------
__device__ __forceinline__ uint32_t smem_u32_of(const void* p) {
    uint32_t a;
    asm("{ .reg .u64 t; cvta.to.shared.u64 t, %1; cvt.u32.u64 %0, t; }"
        : "=r"(a) : "l"(p));
    return a;
}

#define CP16(dst, src) \
    asm volatile("cp.async.cg.shared.global [%0], [%1], 16;" \
                 :: "r"(dst), "l"(src))
#define CP_COMMIT() asm volatile("cp.async.commit_group;" ::: "memory")
#define CP_WAIT(n)  asm volatile("cp.async.wait_group %0;" :: "n"(n) : "memory")

#define LDSM_X4(r0, r1, r2, r3, addr) \
    asm volatile("ldmatrix.sync.aligned.m8n8.x4.shared.b16 {%0,%1,%2,%3}, [%4];" \
                 : "=r"(r0), "=r"(r1), "=r"(r2), "=r"(r3) : "r"(addr))

#define MMA_FP16(d, a, b0, b1) \
    asm volatile("mma.sync.aligned.m16n8k16.row.col.f32.f16.f16.f32 " \
                 "{%0,%1,%2,%3}, {%4,%5,%6,%7}, {%8,%9}, {%0,%1,%2,%3};" \
                 : "+f"((d)[0]), "+f"((d)[1]), "+f"((d)[2]), "+f"((d)[3]) \
                 : "r"((a)[0]), "r"((a)[1]), "r"((a)[2]), "r"((a)[3]), \
                   "r"(b0), "r"(b1))

// swizzled byte offset: 128B rows, 8 x 16B granules, XOR by row&7
__device__ __forceinline__ uint32_t swz(uint32_t row, uint32_t g) {
    return row * 128u + ((g ^ (row & 7u)) << 4);
}

// ---------------------------------------------------------------------------
// Pre-kernels
// ---------------------------------------------------------------------------
__global__ void prep_w(const float* __restrict__ W,
                       const float* __restrict__ A,
                       const float* __restrict__ B) {
    int idx = blockIdx.x * blockDim.x + threadIdx.x;
    int o = idx >> 11, a = idx & 2047;
    float acc = W[idx];
#pragma unroll
    for (int r = 0; r < RANK; r++)
        acc += SCALING * __ldg(&B[o * RANK + r]) * __ldg(&A[r * K_DIM + a]);
    __half hi = __float2half(acc);
    g_wh[idx] = hi;
    g_wl[idx] = __float2half(acc - __half2float(hi));
}

__global__ void prep_x(const float* __restrict__ x,
                       const int* __restrict__ in_idx) {
    int idx = blockIdx.x * blockDim.x + threadIdx.x;
    int n = idx >> 11, a = idx & 2047;
    g_xh[idx] = __float2half(__ldg(&x[(size_t)n * IN_COLS + __ldg(&in_idx[a])]));
}

__global__ void zero_out(float4* __restrict__ out) {
    int idx = blockIdx.x * blockDim.x + threadIdx.x;
    out[idx] = make_float4(0.f, 0.f, 0.f, 0.f);
}

// ---------------------------------------------------------------------------
// cp.async chunk loader: 256 threads, 12 x 16B each
// ---------------------------------------------------------------------------
__device__ __forceinline__ void load_chunk(uint32_t su, int s, int tmBase,
                                           int tnBase, int c, int tid) {
    const uint32_t sb = su + s * STAGE;
    const size_t kOff = (size_t)c * KC;
#pragma unroll
    for (int it = 0; it < 4; it++) {          // A: 128 rows x 8 granules
        int u = tid + it * NTHREADS;
        int r = u >> 3, g = u & 7;
        size_t goff = (size_t)(tmBase + r) * K_DIM + kOff + g * 8;
        CP16(sb + OFF_A + swz(r, g), (const char*)(g_xh + goff));
    }
#pragma unroll
    for (int it = 0; it < 4; it++) {          // B hi/lo: 128 rows x 8 granules
        int u = tid + it * NTHREADS;
        int r = u >> 3, g = u & 7;
        size_t goff = (size_t)(tnBase + r) * K_DIM + kOff + g * 8;
        CP16(sb + OFF_BH + swz(r, g), (const char*)(g_wh + goff));
        CP16(sb + OFF_BL + swz(r, g), (const char*)(g_wl + goff));
    }
}

// ---------------------------------------------------------------------------
// fp16 2-product mma.sync GEMM + fused bias/scatter epilogue
// ---------------------------------------------------------------------------
__global__ void __launch_bounds__(NTHREADS, 1)
gemm_mma(const float* __restrict__ bias,
         const int*   __restrict__ oidx,
         float*       __restrict__ out) {
    extern __shared__ __align__(128) char smraw[];
    const uint32_t su = smem_u32_of(smraw);

    const int tid  = threadIdx.x;
    const int lane = tid & 31;
    const int wid  = tid >> 5;                 // 0..7
    const int mBase = (wid & 1) * 64;          // warp m offset
    const int nBase = (wid >> 1) * 32;         // warp n offset
    const int tnBase = blockIdx.x * NT;
    const int tmBase = blockIdx.y * MT;

    // ldmatrix per-thread row mapping (validated in R7)
    const int aRow0 = mBase + (lane & 7) + ((lane >> 3) & 1) * 8;   // + mi*16
    const int aGsel = (lane >> 4) & 1;
    const int bRow0 = nBase + (lane & 7) + ((lane >> 4) & 1) * 8;   // + nj*16
    const int bGsel = (lane >> 3) & 1;

    float acc[4][4][4];
#pragma unroll
    for (int i = 0; i < 4; i++)
#pragma unroll
        for (int j = 0; j < 4; j++)
#pragma unroll
            for (int q = 0; q < 4; q++) acc[i][j][q] = 0.f;

    // prologue: fill STAGES-1 stages
#pragma unroll
    for (int s = 0; s < STAGES - 1; s++) {
        load_chunk(su, s, tmBase, tnBase, s, tid);
        CP_COMMIT();
    }

    for (int c = 0; c < NCHUNK; c++) {
        CP_WAIT(2);            // stage c complete (c+1, c+2 may be in flight)
        __syncthreads();       // all warps see stage c; all done with stage c-1
        if (c + STAGES - 1 < NCHUNK)
            load_chunk(su, (c + STAGES - 1) & (STAGES - 1), tmBase, tnBase,
                       c + STAGES - 1, tid);
        CP_COMMIT();           // unconditional: keeps group count uniform

        const uint32_t sb = su + (c & (STAGES - 1)) * STAGE;
#pragma unroll
        for (int ks = 0; ks < 4; ks++) {
            const uint32_t gA = 2 * ks + aGsel;
            const uint32_t gB = 2 * ks + bGsel;
            uint32_t a[4][4];
#pragma unroll
            for (int mi = 0; mi < 4; mi++) {
                const uint32_t off = swz(aRow0 + mi * 16, gA);
                LDSM_X4(a[mi][0], a[mi][1], a[mi][2], a[mi][3],
                        sb + OFF_A + off);
            }
#pragma unroll
            for (int nj = 0; nj < 2; nj++) {
                const uint32_t off = swz(bRow0 + nj * 16, gB);
                uint32_t bh[4], bl[4];
                LDSM_X4(bh[0], bh[1], bh[2], bh[3], sb + OFF_BH + off);
                LDSM_X4(bl[0], bl[1], bl[2], bl[3], sb + OFF_BL + off);
#pragma unroll
                for (int mi = 0; mi < 4; mi++) {
                    MMA_FP16(acc[mi][nj * 2 + 0], a[mi], bh[0], bh[1]);
                    MMA_FP16(acc[mi][nj * 2 + 1], a[mi], bh[2], bh[3]);
                    MMA_FP16(acc[mi][nj * 2 + 0], a[mi], bl[0], bl[1]);
                    MMA_FP16(acc[mi][nj * 2 + 1], a[mi], bl[2], bl[3]);
                }
            }
        }
    }

    // epilogue: bias + scatter straight from registers
#pragma unroll
    for (int mi = 0; mi < 4; mi++) {
        const int mRow = tmBase + mBase + mi * 16 + (lane >> 2);
        float* orow0 = out + (size_t)mRow * OUT_COLS;
        float* orow1 = out + (size_t)(mRow + 8) * OUT_COLS;
#pragma unroll
        for (int nf = 0; nf < 4; nf++) {
            const int nCol = tnBase + nBase + (nf >> 1) * 16 + (nf & 1) * 8
                           + (lane & 3) * 2;
            const int o0 = __ldg(&oidx[nCol]);
            const int o1 = __ldg(&oidx[nCol + 1]);
            const float b0 = __ldg(&bias[nCol]);
            const float b1 = __ldg(&bias[nCol + 1]);
            orow0[o0] = acc[mi][nf][0] + b0;
            orow0[o1] = acc[mi][nf][1] + b1;
            orow1[o0] = acc[mi][nf][2] + b0;
            orow1[o1] = acc[mi][nf][3] + b1;
        }
    }
}

// ---------------------------------------------------------------------------
extern "C" void kernel_launch(void* const* d_in, const int* in_sizes, int n_in,
                              void* d_out, int out_size) {
    const float* x       = (const float*)d_in[0];
    const float* W       = (const float*)d_in[1];
    const float* b       = (const float*)d_in[2];
    const float* lA      = (const float*)d_in[3];
    const float* lB      = (const float*)d_in[4];
    const int*   in_idx  = (const int*)d_in[5];
    const int*   out_idx = (const int*)d_in[6];
    float*       out     = (float*)d_out;

    cudaFuncSetAttribute(gemm_mma, cudaFuncAttributeMaxDynamicSharedMemorySize,
                         SMEM_BYTES);

    prep_w<<<(N_DIM * K_DIM) / 256, 256>>>(W, lA, lB);
    prep_x<<<(M_ROWS * K_DIM) / 256, 256>>>(x, in_idx);
    zero_out<<<(M_ROWS * OUT_COLS / 4) / 256, 256>>>((float4*)out);

    dim3 grid(N_DIM / NT, M_ROWS / MT);   // (16, 64)
    gemm_mma<<<grid, NTHREADS, SMEM_BYTES>>>(b, out_idx, out);
}